// round 15
// baseline (speedup 1.0000x reference)
#include <cuda_runtime.h>
#include <cuda_bf16.h>

#define BB 4
#define NBND 262144
#define NATM 8192
#define FF 32
#define NTILE 8192
#define PGRID 592

typedef unsigned long long u64;

__device__ float g_bta[BB * NATM * FF];
__device__ float g_cnt[BB * NATM];
__device__ float g_part[2][32][32];
__device__ unsigned int g_done;
__device__ __align__(16) float g_pa[BB * NATM * 64];
__device__ __align__(16) float g_pb[BB * NATM * 64];

__device__ __forceinline__ float softplus(float x) {
    return fmaxf(x, 0.0f) + __logf(1.0f + __expf(-fabsf(x)));
}
__device__ __forceinline__ u64 pack2(float lo, float hi) {
    u64 r; asm("mov.b64 %0, {%1, %2};" : "=l"(r) : "f"(lo), "f"(hi)); return r;
}
__device__ __forceinline__ u64 pack2s(float x) { return pack2(x, x); }
__device__ __forceinline__ void unpack2(u64 v, float& lo, float& hi) {
    asm("mov.b64 {%0, %1}, %2;" : "=f"(lo), "=f"(hi) : "l"(v));
}
__device__ __forceinline__ void fma2(u64& d, u64 a, u64 b) {
    asm("fma.rn.f32x2 %0, %1, %2, %0;" : "+l"(d) : "l"(a), "l"(b));
}
__device__ __forceinline__ void red4(float* p, float a, float b, float c, float d) {
    asm volatile("red.global.add.v4.f32 [%0], {%1, %2, %3, %4};"
                 :: "l"(p), "f"(a), "f"(b), "f"(c), "f"(d) : "memory");
}

__global__ void zero_kernel() {
    long i = (long)blockIdx.x * 256 + threadIdx.x;
    if (i < (long)BB * NATM * FF) g_bta[i] = 0.0f;
    if (i < BB * NATM) g_cnt[i] = 0.0f;
    if (i == 0) g_done = 0u;
}

// ---------------- atom_pre: warp-tiled (round-13 proven) ----------------
__global__ void __launch_bounds__(128, 4) atom_pre_kernel(
    const float* __restrict__ atoms, const float* __restrict__ w1,
    const float* __restrict__ b1, const float* __restrict__ state)
{
    __shared__ __align__(16) float sX[32 * 128];
    __shared__ __align__(16) float s_hst[64];

    const int tid = threadIdx.x;
    const int w = tid >> 5;
    const int lane = tid & 31;
    const int ti = lane & 3;
    const int tj = lane >> 2;
    const int j0 = tj * 8;
    const int c0 = w * 32 + ti * 8;
    const int ch0 = c0 >> 2;
    const long row0 = (long)blockIdx.x * 128;
    const int b = blockIdx.x >> 6;

    if (tid < 64) {
        float acc = __ldg(&b1[tid]);
        #pragma unroll
        for (int k = 0; k < 32; k++)
            acc = fmaf(__ldg(&state[b * FF + k]), __ldg(&w1[(96 + k) * 64 + tid]), acc);
        s_hst[tid] = acc;
    }
    {
        const float4* p = (const float4*)(atoms + (row0 + tid) * FF);
        const int cch = tid >> 2, cw = tid & 3;
        #pragma unroll
        for (int q = 0; q < 8; q++) {
            float4 v = __ldg(&p[q]);
            float vv[4] = {v.x, v.y, v.z, v.w};
            #pragma unroll
            for (int r = 0; r < 4; r++) {
                int k = 4 * q + r;
                sX[k * 128 + (((cch ^ ((k >> 3) & 7)) << 2) | cw)] = vv[r];
            }
        }
    }
    __syncthreads();

    u64 acc[8][4];
    {
        const float4 hA = *(const float4*)&s_hst[j0];
        const float4 hB = *(const float4*)&s_hst[j0 + 4];
        #pragma unroll
        for (int s = 0; s < 8; s++) {
            acc[s][0] = pack2(hA.x, hA.y);
            acc[s][1] = pack2(hA.z, hA.w);
            acc[s][2] = pack2(hB.x, hB.y);
            acc[s][3] = pack2(hB.z, hB.w);
        }
    }
    #pragma unroll 4
    for (int k = 0; k < 32; k++) {
        const int K = (k >> 3) & 7;
        const float4 x0 = *(const float4*)&sX[k * 128 + ((ch0 ^ K) << 2)];
        const float4 x1 = *(const float4*)&sX[k * 128 + (((ch0 + 1) ^ K) << 2)];
        const ulonglong2 wA = __ldg((const ulonglong2*)(w1 + k * 64 + j0));
        const ulonglong2 wB = __ldg((const ulonglong2*)(w1 + k * 64 + j0 + 4));
        const float xs[8] = {x0.x, x0.y, x0.z, x0.w, x1.x, x1.y, x1.z, x1.w};
        #pragma unroll
        for (int s = 0; s < 8; s++) {
            const u64 x2 = pack2s(xs[s]);
            fma2(acc[s][0], x2, wA.x);
            fma2(acc[s][1], x2, wA.y);
            fma2(acc[s][2], x2, wB.x);
            fma2(acc[s][3], x2, wB.y);
        }
    }
    #pragma unroll
    for (int s = 0; s < 8; s++) {
        float* dst = g_pa + (row0 + c0 + s) * 64 + j0;
        float v0, v1, v2, v3;
        unpack2(acc[s][0], v0, v1);
        unpack2(acc[s][1], v2, v3);
        *(float4*)dst = make_float4(v0, v1, v2, v3);
        unpack2(acc[s][2], v0, v1);
        unpack2(acc[s][3], v2, v3);
        *(float4*)(dst + 4) = make_float4(v0, v1, v2, v3);
    }

    #pragma unroll
    for (int s = 0; s < 8; s++)
        #pragma unroll
        for (int jp = 0; jp < 4; jp++) acc[s][jp] = 0ull;
    #pragma unroll 4
    for (int k = 0; k < 32; k++) {
        const int K = (k >> 3) & 7;
        const float4 x0 = *(const float4*)&sX[k * 128 + ((ch0 ^ K) << 2)];
        const float4 x1 = *(const float4*)&sX[k * 128 + (((ch0 + 1) ^ K) << 2)];
        const ulonglong2 wA = __ldg((const ulonglong2*)(w1 + (32 + k) * 64 + j0));
        const ulonglong2 wB = __ldg((const ulonglong2*)(w1 + (32 + k) * 64 + j0 + 4));
        const float xs[8] = {x0.x, x0.y, x0.z, x0.w, x1.x, x1.y, x1.z, x1.w};
        #pragma unroll
        for (int s = 0; s < 8; s++) {
            const u64 x2 = pack2s(xs[s]);
            fma2(acc[s][0], x2, wA.x);
            fma2(acc[s][1], x2, wA.y);
            fma2(acc[s][2], x2, wB.x);
            fma2(acc[s][3], x2, wB.y);
        }
    }
    #pragma unroll
    for (int s = 0; s < 8; s++) {
        float* dst = g_pb + (row0 + c0 + s) * 64 + j0;
        float v0, v1, v2, v3;
        unpack2(acc[s][0], v0, v1);
        unpack2(acc[s][1], v2, v3);
        *(float4*)dst = make_float4(v0, v1, v2, v3);
        unpack2(acc[s][2], v0, v1);
        unpack2(acc[s][3], v2, v3);
        *(float4*)(dst + 4) = make_float4(v0, v1, v2, v3);
    }
}

// ---------------- bond kernel: persistent blocks, round-10 inner code ----------------
__global__ void __launch_bounds__(128, 4) bond_kernel(
    const float* __restrict__ bonds, const int* __restrict__ ba1,
    const int* __restrict__ ba2,
    const float* __restrict__ w1, const float* __restrict__ w2,
    const float* __restrict__ b2v, const float* __restrict__ w3,
    const float* __restrict__ b3v, float* __restrict__ out_bonds)
{
    __shared__ __align__(16) float sW2[64 * 64];
    __shared__ __align__(16) float sX[64 * 128];

    const int tid = threadIdx.x;
    const int w = tid >> 5;
    const int lane = tid & 31;
    const int ti = lane & 3;
    const int tj = lane >> 2;
    const int j0 = tj * 8;
    const int c0 = w * 32 + ti * 8;
    const int ch0 = c0 >> 2;
    const int j0b = tj * 4;

    // stage W2 once per persistent block
    for (int i = tid; i < 1024; i += 128)
        ((float4*)sW2)[i] = __ldg(&((const float4*)w2)[i]);

    for (int tile = blockIdx.x; tile < NTILE; tile += PGRID) {
        const long row0 = (long)tile * 128;
        const int b = tile >> 11;

        __syncthreads();   // prior tile's sX reads complete before restaging
        {
            const float4* p = (const float4*)(bonds + (row0 + tid) * FF);
            const int cch = tid >> 2, cw = tid & 3;
            #pragma unroll
            for (int q = 0; q < 8; q++) {
                float4 v = __ldg(&p[q]);
                float vv[4] = {v.x, v.y, v.z, v.w};
                #pragma unroll
                for (int r = 0; r < 4; r++) {
                    int k = 4 * q + r;
                    sX[k * 128 + (((cch ^ ((k >> 3) & 7)) << 2) | cw)] = vv[r];
                }
            }
        }
        __syncthreads();

        u64 acc[8][4];
        #pragma unroll
        for (int s = 0; s < 8; s++)
            #pragma unroll
            for (int jp = 0; jp < 4; jp++) acc[s][jp] = 0ull;

        #pragma unroll 4
        for (int k = 0; k < 32; k++) {
            const int K = (k >> 3) & 7;
            const float4 x0 = *(const float4*)&sX[k * 128 + ((ch0 ^ K) << 2)];
            const float4 x1 = *(const float4*)&sX[k * 128 + (((ch0 + 1) ^ K) << 2)];
            const ulonglong2 wA = __ldg((const ulonglong2*)(w1 + (64 + k) * 64 + j0));
            const ulonglong2 wB = __ldg((const ulonglong2*)(w1 + (64 + k) * 64 + j0 + 4));
            const float xs[8] = {x0.x, x0.y, x0.z, x0.w, x1.x, x1.y, x1.z, x1.w};
            #pragma unroll
            for (int s = 0; s < 8; s++) {
                const u64 x2 = pack2s(xs[s]);
                fma2(acc[s][0], x2, wA.x);
                fma2(acc[s][1], x2, wA.y);
                fma2(acc[s][2], x2, wB.x);
                fma2(acc[s][3], x2, wB.y);
            }
        }
        __syncthreads();

        #pragma unroll
        for (int s = 0; s < 8; s++) {
            const long row = row0 + c0 + s;
            const int a1 = __ldg(&ba1[row]);
            const int a2 = __ldg(&ba2[row]);
            const float* pap = g_pa + ((long)b * NATM + a1) * 64 + j0;
            const float* pbp = g_pb + ((long)b * NATM + a2) * 64 + j0;
            float4 A0 = __ldg((const float4*)pap), A1 = __ldg((const float4*)(pap + 4));
            float4 B0 = __ldg((const float4*)pbp), B1 = __ldg((const float4*)(pbp + 4));
            float v0, v1;
            unpack2(acc[s][0], v0, v1);
            acc[s][0] = pack2(softplus(v0 + A0.x + B0.x), softplus(v1 + A0.y + B0.y));
            unpack2(acc[s][1], v0, v1);
            acc[s][1] = pack2(softplus(v0 + A0.z + B0.z), softplus(v1 + A0.w + B0.w));
            unpack2(acc[s][2], v0, v1);
            acc[s][2] = pack2(softplus(v0 + A1.x + B1.x), softplus(v1 + A1.y + B1.y));
            unpack2(acc[s][3], v0, v1);
            acc[s][3] = pack2(softplus(v0 + A1.z + B1.z), softplus(v1 + A1.w + B1.w));
        }
        #pragma unroll
        for (int jj = 0; jj < 8; jj++) {
            const int r = j0 + jj;
            const int S = (r >> 3) & 7;
            const int jp = jj >> 1;
            float t0, t1, t2, t3, t4, t5, t6, t7, lo, hi;
            unpack2(acc[0][jp], lo, hi); t0 = (jj & 1) ? hi : lo;
            unpack2(acc[1][jp], lo, hi); t1 = (jj & 1) ? hi : lo;
            unpack2(acc[2][jp], lo, hi); t2 = (jj & 1) ? hi : lo;
            unpack2(acc[3][jp], lo, hi); t3 = (jj & 1) ? hi : lo;
            unpack2(acc[4][jp], lo, hi); t4 = (jj & 1) ? hi : lo;
            unpack2(acc[5][jp], lo, hi); t5 = (jj & 1) ? hi : lo;
            unpack2(acc[6][jp], lo, hi); t6 = (jj & 1) ? hi : lo;
            unpack2(acc[7][jp], lo, hi); t7 = (jj & 1) ? hi : lo;
            *(float4*)&sX[r * 128 + ((ch0 ^ S) << 2)] = make_float4(t0, t1, t2, t3);
            *(float4*)&sX[r * 128 + (((ch0 + 1) ^ S) << 2)] = make_float4(t4, t5, t6, t7);
        }
        __syncthreads();

        #pragma unroll
        for (int s = 0; s < 8; s++)
            #pragma unroll
            for (int jp = 0; jp < 4; jp++) acc[s][jp] = 0ull;
        for (int kk = 0; kk < 64; kk += 8) {
            const int K = kk >> 3;
            const float* xr = &sX[kk * 128];
            const float* wr = &sW2[kk * 64];
            #pragma unroll
            for (int u = 0; u < 8; u++) {
                const float4 x0 = *(const float4*)&xr[u * 128 + ((ch0 ^ K) << 2)];
                const float4 x1 = *(const float4*)&xr[u * 128 + (((ch0 + 1) ^ K) << 2)];
                const ulonglong2 wA = *(const ulonglong2*)&wr[u * 64 + j0];
                const ulonglong2 wB = *(const ulonglong2*)&wr[u * 64 + j0 + 4];
                const float xs[8] = {x0.x, x0.y, x0.z, x0.w, x1.x, x1.y, x1.z, x1.w};
                #pragma unroll
                for (int s = 0; s < 8; s++) {
                    const u64 x2 = pack2s(xs[s]);
                    fma2(acc[s][0], x2, wA.x);
                    fma2(acc[s][1], x2, wA.y);
                    fma2(acc[s][2], x2, wB.x);
                    fma2(acc[s][3], x2, wB.y);
                }
            }
        }
        __syncthreads();

        {
            float4 bA = __ldg((const float4*)(b2v + j0));
            float4 bB = __ldg((const float4*)(b2v + j0 + 4));
            #pragma unroll
            for (int s = 0; s < 8; s++) {
                float v0, v1;
                unpack2(acc[s][0], v0, v1);
                acc[s][0] = pack2(softplus(v0 + bA.x), softplus(v1 + bA.y));
                unpack2(acc[s][1], v0, v1);
                acc[s][1] = pack2(softplus(v0 + bA.z), softplus(v1 + bA.w));
                unpack2(acc[s][2], v0, v1);
                acc[s][2] = pack2(softplus(v0 + bB.x), softplus(v1 + bB.y));
                unpack2(acc[s][3], v0, v1);
                acc[s][3] = pack2(softplus(v0 + bB.z), softplus(v1 + bB.w));
            }
            #pragma unroll
            for (int jj = 0; jj < 8; jj++) {
                const int r = j0 + jj;
                const int S = (r >> 3) & 7;
                const int jp = jj >> 1;
                float t0, t1, t2, t3, t4, t5, t6, t7, lo, hi;
                unpack2(acc[0][jp], lo, hi); t0 = (jj & 1) ? hi : lo;
                unpack2(acc[1][jp], lo, hi); t1 = (jj & 1) ? hi : lo;
                unpack2(acc[2][jp], lo, hi); t2 = (jj & 1) ? hi : lo;
                unpack2(acc[3][jp], lo, hi); t3 = (jj & 1) ? hi : lo;
                unpack2(acc[4][jp], lo, hi); t4 = (jj & 1) ? hi : lo;
                unpack2(acc[5][jp], lo, hi); t5 = (jj & 1) ? hi : lo;
                unpack2(acc[6][jp], lo, hi); t6 = (jj & 1) ? hi : lo;
                unpack2(acc[7][jp], lo, hi); t7 = (jj & 1) ? hi : lo;
                *(float4*)&sX[r * 128 + ((ch0 ^ S) << 2)] = make_float4(t0, t1, t2, t3);
                *(float4*)&sX[r * 128 + (((ch0 + 1) ^ S) << 2)] = make_float4(t4, t5, t6, t7);
            }
        }
        __syncthreads();

        u64 a3[8][2];
        #pragma unroll
        for (int s = 0; s < 8; s++) { a3[s][0] = 0ull; a3[s][1] = 0ull; }
        for (int kk = 0; kk < 64; kk += 8) {
            const int K = kk >> 3;
            const float* xr = &sX[kk * 128];
            #pragma unroll
            for (int u = 0; u < 8; u++) {
                const float4 x0 = *(const float4*)&xr[u * 128 + ((ch0 ^ K) << 2)];
                const float4 x1 = *(const float4*)&xr[u * 128 + (((ch0 + 1) ^ K) << 2)];
                const ulonglong2 wv = __ldg((const ulonglong2*)(w3 + (kk + u) * 32 + j0b));
                const float xs[8] = {x0.x, x0.y, x0.z, x0.w, x1.x, x1.y, x1.z, x1.w};
                #pragma unroll
                for (int s = 0; s < 8; s++) {
                    const u64 x2 = pack2s(xs[s]);
                    fma2(a3[s][0], x2, wv.x);
                    fma2(a3[s][1], x2, wv.y);
                }
            }
        }

        {
            float4 b3q = __ldg((const float4*)(b3v + j0b));
            #pragma unroll
            for (int s = 0; s < 8; s++) {
                const long row = row0 + c0 + s;
                const int a1 = __ldg(&ba1[row]);
                float o0, o1, o2, o3;
                unpack2(a3[s][0], o0, o1);
                unpack2(a3[s][1], o2, o3);
                o0 = softplus(o0 + b3q.x);
                o1 = softplus(o1 + b3q.y);
                o2 = softplus(o2 + b3q.z);
                o3 = softplus(o3 + b3q.w);
                *(float4*)(out_bonds + row * FF + j0b) = make_float4(o0, o1, o2, o3);
                red4(g_bta + ((long)b * NATM + a1) * FF + j0b, o0, o1, o2, o3);
                if (tj == 0) atomicAdd(&g_cnt[b * NATM + a1], 1.0f);
            }
        }
    }
}

// ---------------- atom main kernel (round-12 proven, unchanged) ----------------
__global__ void __launch_bounds__(128, 4) atom_main_kernel(
    const float* __restrict__ atoms, const float* __restrict__ state,
    const float* __restrict__ w1, const float* __restrict__ b1,
    const float* __restrict__ w2, const float* __restrict__ b2v,
    const float* __restrict__ w3, const float* __restrict__ b3v,
    float* __restrict__ out_atoms)
{
    __shared__ __align__(16) float sW2[64 * 64];
    __shared__ __align__(16) float sX[64 * 128];
    __shared__ __align__(16) float s_hst[64];

    const int tid = threadIdx.x;
    const int w = tid >> 5;
    const int lane = tid & 31;
    const int ti = lane & 3;
    const int tj = lane >> 2;
    const int j0 = tj * 8;
    const int c0 = w * 32 + ti * 8;
    const int ch0 = c0 >> 2;
    const long row0 = (long)blockIdx.x * 128;
    const int b = blockIdx.x >> 6;

    for (int i = tid; i < 1024; i += 128)
        ((float4*)sW2)[i] = __ldg(&((const float4*)w2)[i]);

    if (tid < 64) {
        float acc = __ldg(&b1[tid]);
        #pragma unroll
        for (int k = 0; k < 32; k++)
            acc = fmaf(__ldg(&state[b * FF + k]), __ldg(&w1[(64 + k) * 64 + tid]), acc);
        s_hst[tid] = acc;
    }

    {
        const long grow = row0 + tid;
        const float invc = 1.0f / g_cnt[grow];
        const int cch = tid >> 2, cw = tid & 3;
        const float4* pb = (const float4*)(g_bta + grow * FF);
        const float4* pa = (const float4*)(atoms + grow * FF);
        #pragma unroll
        for (int q = 0; q < 8; q++) {
            float4 v = __ldg(&pb[q]);
            float vv[4] = {v.x * invc, v.y * invc, v.z * invc, v.w * invc};
            #pragma unroll
            for (int r = 0; r < 4; r++) {
                int k = 4 * q + r;
                sX[k * 128 + (((cch ^ ((k >> 3) & 7)) << 2) | cw)] = vv[r];
            }
        }
        #pragma unroll
        for (int q = 0; q < 8; q++) {
            float4 v = __ldg(&pa[q]);
            float vv[4] = {v.x, v.y, v.z, v.w};
            #pragma unroll
            for (int r = 0; r < 4; r++) {
                int k = 32 + 4 * q + r;
                sX[k * 128 + (((cch ^ ((k >> 3) & 7)) << 2) | cw)] = vv[r];
            }
        }
    }
    __syncthreads();

    u64 acc[8][4];
    #pragma unroll
    for (int s = 0; s < 8; s++)
        #pragma unroll
        for (int jp = 0; jp < 4; jp++) acc[s][jp] = 0ull;

    for (int kk = 0; kk < 64; kk += 8) {
        const int K = kk >> 3;
        const float* xr = &sX[kk * 128];
        #pragma unroll
        for (int u = 0; u < 8; u++) {
            const float4 x0 = *(const float4*)&xr[u * 128 + ((ch0 ^ K) << 2)];
            const float4 x1 = *(const float4*)&xr[u * 128 + (((ch0 + 1) ^ K) << 2)];
            const ulonglong2 wA = __ldg((const ulonglong2*)(w1 + (kk + u) * 64 + j0));
            const ulonglong2 wB = __ldg((const ulonglong2*)(w1 + (kk + u) * 64 + j0 + 4));
            const float xs[8] = {x0.x, x0.y, x0.z, x0.w, x1.x, x1.y, x1.z, x1.w};
            #pragma unroll
            for (int s = 0; s < 8; s++) {
                const u64 x2 = pack2s(xs[s]);
                fma2(acc[s][0], x2, wA.x);
                fma2(acc[s][1], x2, wA.y);
                fma2(acc[s][2], x2, wB.x);
                fma2(acc[s][3], x2, wB.y);
            }
        }
    }
    __syncthreads();

    {
        const float4 hA = *(const float4*)&s_hst[j0];
        const float4 hB = *(const float4*)&s_hst[j0 + 4];
        #pragma unroll
        for (int s = 0; s < 8; s++) {
            float v0, v1;
            unpack2(acc[s][0], v0, v1);
            acc[s][0] = pack2(softplus(v0 + hA.x), softplus(v1 + hA.y));
            unpack2(acc[s][1], v0, v1);
            acc[s][1] = pack2(softplus(v0 + hA.z), softplus(v1 + hA.w));
            unpack2(acc[s][2], v0, v1);
            acc[s][2] = pack2(softplus(v0 + hB.x), softplus(v1 + hB.y));
            unpack2(acc[s][3], v0, v1);
            acc[s][3] = pack2(softplus(v0 + hB.z), softplus(v1 + hB.w));
        }
        #pragma unroll
        for (int jj = 0; jj < 8; jj++) {
            const int r = j0 + jj;
            const int S = (r >> 3) & 7;
            const int jp = jj >> 1;
            float t0, t1, t2, t3, t4, t5, t6, t7, lo, hi;
            unpack2(acc[0][jp], lo, hi); t0 = (jj & 1) ? hi : lo;
            unpack2(acc[1][jp], lo, hi); t1 = (jj & 1) ? hi : lo;
            unpack2(acc[2][jp], lo, hi); t2 = (jj & 1) ? hi : lo;
            unpack2(acc[3][jp], lo, hi); t3 = (jj & 1) ? hi : lo;
            unpack2(acc[4][jp], lo, hi); t4 = (jj & 1) ? hi : lo;
            unpack2(acc[5][jp], lo, hi); t5 = (jj & 1) ? hi : lo;
            unpack2(acc[6][jp], lo, hi); t6 = (jj & 1) ? hi : lo;
            unpack2(acc[7][jp], lo, hi); t7 = (jj & 1) ? hi : lo;
            *(float4*)&sX[r * 128 + ((ch0 ^ S) << 2)] = make_float4(t0, t1, t2, t3);
            *(float4*)&sX[r * 128 + (((ch0 + 1) ^ S) << 2)] = make_float4(t4, t5, t6, t7);
        }
    }
    __syncthreads();

    #pragma unroll
    for (int s = 0; s < 8; s++)
        #pragma unroll
        for (int jp = 0; jp < 4; jp++) acc[s][jp] = 0ull;
    for (int kk = 0; kk < 64; kk += 8) {
        const int K = kk >> 3;
        const float* xr = &sX[kk * 128];
        const float* wr = &sW2[kk * 64];
        #pragma unroll
        for (int u = 0; u < 8; u++) {
            const float4 x0 = *(const float4*)&xr[u * 128 + ((ch0 ^ K) << 2)];
            const float4 x1 = *(const float4*)&xr[u * 128 + (((ch0 + 1) ^ K) << 2)];
            const ulonglong2 wA = *(const ulonglong2*)&wr[u * 64 + j0];
            const ulonglong2 wB = *(const ulonglong2*)&wr[u * 64 + j0 + 4];
            const float xs[8] = {x0.x, x0.y, x0.z, x0.w, x1.x, x1.y, x1.z, x1.w};
            #pragma unroll
            for (int s = 0; s < 8; s++) {
                const u64 x2 = pack2s(xs[s]);
                fma2(acc[s][0], x2, wA.x);
                fma2(acc[s][1], x2, wA.y);
                fma2(acc[s][2], x2, wB.x);
                fma2(acc[s][3], x2, wB.y);
            }
        }
    }
    __syncthreads();

    {
        float4 bA = __ldg((const float4*)(b2v + j0));
        float4 bB = __ldg((const float4*)(b2v + j0 + 4));
        #pragma unroll
        for (int s = 0; s < 8; s++) {
            float v0, v1;
            unpack2(acc[s][0], v0, v1);
            acc[s][0] = pack2(softplus(v0 + bA.x), softplus(v1 + bA.y));
            unpack2(acc[s][1], v0, v1);
            acc[s][1] = pack2(softplus(v0 + bA.z), softplus(v1 + bA.w));
            unpack2(acc[s][2], v0, v1);
            acc[s][2] = pack2(softplus(v0 + bB.x), softplus(v1 + bB.y));
            unpack2(acc[s][3], v0, v1);
            acc[s][3] = pack2(softplus(v0 + bB.z), softplus(v1 + bB.w));
        }
        #pragma unroll
        for (int jj = 0; jj < 8; jj++) {
            const int r = j0 + jj;
            const int S = (r >> 3) & 7;
            const int jp = jj >> 1;
            float t0, t1, t2, t3, t4, t5, t6, t7, lo, hi;
            unpack2(acc[0][jp], lo, hi); t0 = (jj & 1) ? hi : lo;
            unpack2(acc[1][jp], lo, hi); t1 = (jj & 1) ? hi : lo;
            unpack2(acc[2][jp], lo, hi); t2 = (jj & 1) ? hi : lo;
            unpack2(acc[3][jp], lo, hi); t3 = (jj & 1) ? hi : lo;
            unpack2(acc[4][jp], lo, hi); t4 = (jj & 1) ? hi : lo;
            unpack2(acc[5][jp], lo, hi); t5 = (jj & 1) ? hi : lo;
            unpack2(acc[6][jp], lo, hi); t6 = (jj & 1) ? hi : lo;
            unpack2(acc[7][jp], lo, hi); t7 = (jj & 1) ? hi : lo;
            *(float4*)&sX[r * 128 + ((ch0 ^ S) << 2)] = make_float4(t0, t1, t2, t3);
            *(float4*)&sX[r * 128 + (((ch0 + 1) ^ S) << 2)] = make_float4(t4, t5, t6, t7);
        }
    }
    __syncthreads();

    const int j0b = tj * 4;
    u64 a3[8][2];
    #pragma unroll
    for (int s = 0; s < 8; s++) { a3[s][0] = 0ull; a3[s][1] = 0ull; }
    for (int kk = 0; kk < 64; kk += 8) {
        const int K = kk >> 3;
        const float* xr = &sX[kk * 128];
        #pragma unroll
        for (int u = 0; u < 8; u++) {
            const float4 x0 = *(const float4*)&xr[u * 128 + ((ch0 ^ K) << 2)];
            const float4 x1 = *(const float4*)&xr[u * 128 + (((ch0 + 1) ^ K) << 2)];
            const ulonglong2 wv = __ldg((const ulonglong2*)(w3 + (kk + u) * 32 + j0b));
            const float xs[8] = {x0.x, x0.y, x0.z, x0.w, x1.x, x1.y, x1.z, x1.w};
            #pragma unroll
            for (int s = 0; s < 8; s++) {
                const u64 x2 = pack2s(xs[s]);
                fma2(a3[s][0], x2, wv.x);
                fma2(a3[s][1], x2, wv.y);
            }
        }
    }

    {
        float4 b3q = __ldg((const float4*)(b3v + j0b));
        #pragma unroll
        for (int s = 0; s < 8; s++) {
            const long row = row0 + c0 + s;
            float o0, o1, o2, o3;
            unpack2(a3[s][0], o0, o1);
            unpack2(a3[s][1], o2, o3);
            o0 = softplus(o0 + b3q.x);
            o1 = softplus(o1 + b3q.y);
            o2 = softplus(o2 + b3q.z);
            o3 = softplus(o3 + b3q.w);
            *(float4*)(out_atoms + row * FF + j0b) = make_float4(o0, o1, o2, o3);
        }
    }
}

// ---------------- reduce + state (fused, round-14) ----------------
__global__ void __launch_bounds__(256) reduce_state_kernel(
    const float* __restrict__ out_atoms, const float* __restrict__ state,
    const float* __restrict__ w1, const float* __restrict__ b1,
    const float* __restrict__ w2, const float* __restrict__ b2,
    const float* __restrict__ w3, const float* __restrict__ b3,
    float* __restrict__ out_state)
{
    __shared__ float red[2][8][32];
    __shared__ unsigned int s_ticket;
    __shared__ float s_u[BB][96];
    __shared__ float s_h1[BB][64];
    __shared__ float s_h2[BB][64];

    const int blk = blockIdx.x;
    const int bb = blk >> 3;
    const int seg = blk & 7;
    const int t = threadIdx.x;
    const int f = t & 31;
    const int g = t >> 5;
    const long base = ((long)bb * NATM + seg * 1024) * FF;
    float sb = 0.0f, sa = 0.0f;
    for (int r = g; r < 1024; r += 8) {
        sb += g_bta[base + (long)r * FF + f];
        sa += __ldg(&out_atoms[base + (long)r * FF + f]);
    }
    red[0][g][f] = sb;
    red[1][g][f] = sa;
    __syncthreads();
    if (g == 0) {
        float vb = 0.0f, va = 0.0f;
        #pragma unroll
        for (int i = 0; i < 8; i++) { vb += red[0][i][f]; va += red[1][i][f]; }
        g_part[0][blk][f] = vb;
        g_part[1][blk][f] = va;
    }
    __threadfence();
    __syncthreads();
    if (t == 0) s_ticket = atomicAdd(&g_done, 1u);
    __syncthreads();
    if (s_ticket != 31u) return;

    const int b = t >> 6;
    const int u = t & 63;
    if (u < 32) {
        float vb = 0.0f, va = 0.0f;
        #pragma unroll
        for (int s = 0; s < 8; s++) {
            vb += g_part[0][b * 8 + s][u];
            va += g_part[1][b * 8 + s][u];
        }
        s_u[b][u]      = vb * (1.0f / NBND);
        s_u[b][32 + u] = va * (1.0f / NATM);
        s_u[b][64 + u] = __ldg(&state[b * FF + u]);
    }
    __syncthreads();
    {
        float acc = __ldg(&b1[u]);
        for (int k = 0; k < 96; k++) acc = fmaf(s_u[b][k], __ldg(&w1[k * 64 + u]), acc);
        s_h1[b][u] = softplus(acc);
    }
    __syncthreads();
    {
        float acc = __ldg(&b2[u]);
        for (int k = 0; k < 64; k++) acc = fmaf(s_h1[b][k], __ldg(&w2[k * 64 + u]), acc);
        s_h2[b][u] = softplus(acc);
    }
    __syncthreads();
    if (u < 32) {
        float acc = __ldg(&b3[u]);
        for (int k = 0; k < 64; k++) acc = fmaf(s_h2[b][k], __ldg(&w3[k * 32 + u]), acc);
        out_state[b * FF + u] = softplus(acc);
    }
}

extern "C" void kernel_launch(void* const* d_in, const int* in_sizes, int n_in,
                              void* d_out, int out_size)
{
    const float* bonds = (const float*)d_in[0];
    const int*   ba1   = (const int*)d_in[1];
    const int*   ba2   = (const int*)d_in[2];
    const float* atoms = (const float*)d_in[3];
    const float* state = (const float*)d_in[4];
    const float* ew1 = (const float*)d_in[5];
    const float* eb1 = (const float*)d_in[6];
    const float* ew2 = (const float*)d_in[7];
    const float* eb2 = (const float*)d_in[8];
    const float* ew3 = (const float*)d_in[9];
    const float* eb3 = (const float*)d_in[10];
    const float* vw1 = (const float*)d_in[11];
    const float* vb1 = (const float*)d_in[12];
    const float* vw2 = (const float*)d_in[13];
    const float* vb2 = (const float*)d_in[14];
    const float* vw3 = (const float*)d_in[15];
    const float* vb3 = (const float*)d_in[16];
    const float* uw1 = (const float*)d_in[17];
    const float* ub1 = (const float*)d_in[18];
    const float* uw2 = (const float*)d_in[19];
    const float* ub2 = (const float*)d_in[20];
    const float* uw3 = (const float*)d_in[21];
    const float* ub3 = (const float*)d_in[22];

    float* out = (float*)d_out;
    float* out_bonds = out;
    float* out_atoms = out + (long)BB * NBND * FF;
    float* out_state = out_atoms + (long)BB * NATM * FF;

    zero_kernel<<<(BB * NATM * FF + 255) / 256, 256>>>();
    atom_pre_kernel<<<(BB * NATM) / 128, 128>>>(atoms, ew1, eb1, state);
    bond_kernel<<<PGRID, 128>>>(bonds, ba1, ba2,
                                ew1, ew2, eb2, ew3, eb3, out_bonds);
    atom_main_kernel<<<(BB * NATM) / 128, 128>>>(atoms, state,
                                                 vw1, vb1, vw2, vb2, vw3, vb3, out_atoms);
    reduce_state_kernel<<<32, 256>>>(out_atoms, state, uw1, ub1, uw2, ub2,
                                     uw3, ub3, out_state);
}

// round 16
// speedup vs baseline: 1.0934x; 1.0934x over previous
#include <cuda_runtime.h>
#include <cuda_bf16.h>

#define BB 4
#define NBND 262144
#define NATM 8192
#define FF 32

typedef unsigned long long u64;

__device__ float g_bta[BB * NATM * FF];
__device__ float g_cnt[BB * NATM];
__device__ float g_part[2][32][32];     // [bond|atom][reduce-block][feature]
__device__ unsigned int g_done;
__device__ __align__(16) float g_pa[BB * NATM * 64];  // hst + atoms@W1[0:32]
__device__ __align__(16) float g_pb[BB * NATM * 64];  // atoms@W1[32:64]

__device__ __forceinline__ float softplus(float x) {
    return fmaxf(x, 0.0f) + __logf(1.0f + __expf(-fabsf(x)));
}
__device__ __forceinline__ u64 pack2(float lo, float hi) {
    u64 r; asm("mov.b64 %0, {%1, %2};" : "=l"(r) : "f"(lo), "f"(hi)); return r;
}
__device__ __forceinline__ u64 pack2s(float x) { return pack2(x, x); }
__device__ __forceinline__ void unpack2(u64 v, float& lo, float& hi) {
    asm("mov.b64 {%0, %1}, %2;" : "=f"(lo), "=f"(hi) : "l"(v));
}
__device__ __forceinline__ void fma2(u64& d, u64 a, u64 b) {
    asm("fma.rn.f32x2 %0, %1, %2, %0;" : "+l"(d) : "l"(a), "l"(b));
}
__device__ __forceinline__ void red4(float* p, float a, float b, float c, float d) {
    asm volatile("red.global.add.v4.f32 [%0], {%1, %2, %3, %4};"
                 :: "l"(p), "f"(a), "f"(b), "f"(c), "f"(d) : "memory");
}

__global__ void zero_kernel() {
    long i = (long)blockIdx.x * 256 + threadIdx.x;
    if (i < (long)BB * NATM * FF) g_bta[i] = 0.0f;
    if (i < BB * NATM) g_cnt[i] = 0.0f;
    if (i == 0) g_done = 0u;
}

// ---------------- atom_pre: warp-tiled, block = 128 atoms ----------------
__global__ void __launch_bounds__(128, 4) atom_pre_kernel(
    const float* __restrict__ atoms, const float* __restrict__ w1,
    const float* __restrict__ b1, const float* __restrict__ state)
{
    __shared__ __align__(16) float sX[32 * 128];
    __shared__ __align__(16) float s_hst[64];

    const int tid = threadIdx.x;
    const int w = tid >> 5;
    const int lane = tid & 31;
    const int ti = lane & 3;
    const int tj = lane >> 2;
    const int j0 = tj * 8;
    const int c0 = w * 32 + ti * 8;
    const int ch0 = c0 >> 2;
    const long row0 = (long)blockIdx.x * 128;
    const int b = blockIdx.x >> 6;

    if (tid < 64) {
        float acc = __ldg(&b1[tid]);
        #pragma unroll
        for (int k = 0; k < 32; k++)
            acc = fmaf(__ldg(&state[b * FF + k]), __ldg(&w1[(96 + k) * 64 + tid]), acc);
        s_hst[tid] = acc;
    }

    {
        const float4* p = (const float4*)(atoms + (row0 + tid) * FF);
        const int cch = tid >> 2, cw = tid & 3;
        #pragma unroll
        for (int q = 0; q < 8; q++) {
            float4 v = __ldg(&p[q]);
            float vv[4] = {v.x, v.y, v.z, v.w};
            #pragma unroll
            for (int r = 0; r < 4; r++) {
                int k = 4 * q + r;
                sX[k * 128 + (((cch ^ ((k >> 3) & 7)) << 2) | cw)] = vv[r];
            }
        }
    }
    __syncthreads();

    u64 acc[8][4];

    {
        const float4 hA = *(const float4*)&s_hst[j0];
        const float4 hB = *(const float4*)&s_hst[j0 + 4];
        #pragma unroll
        for (int s = 0; s < 8; s++) {
            acc[s][0] = pack2(hA.x, hA.y);
            acc[s][1] = pack2(hA.z, hA.w);
            acc[s][2] = pack2(hB.x, hB.y);
            acc[s][3] = pack2(hB.z, hB.w);
        }
    }
    #pragma unroll 4
    for (int k = 0; k < 32; k++) {
        const int K = (k >> 3) & 7;
        const float4 x0 = *(const float4*)&sX[k * 128 + ((ch0 ^ K) << 2)];
        const float4 x1 = *(const float4*)&sX[k * 128 + (((ch0 + 1) ^ K) << 2)];
        const ulonglong2 wA = __ldg((const ulonglong2*)(w1 + k * 64 + j0));
        const ulonglong2 wB = __ldg((const ulonglong2*)(w1 + k * 64 + j0 + 4));
        const float xs[8] = {x0.x, x0.y, x0.z, x0.w, x1.x, x1.y, x1.z, x1.w};
        #pragma unroll
        for (int s = 0; s < 8; s++) {
            const u64 x2 = pack2s(xs[s]);
            fma2(acc[s][0], x2, wA.x);
            fma2(acc[s][1], x2, wA.y);
            fma2(acc[s][2], x2, wB.x);
            fma2(acc[s][3], x2, wB.y);
        }
    }
    #pragma unroll
    for (int s = 0; s < 8; s++) {
        float* dst = g_pa + (row0 + c0 + s) * 64 + j0;
        float v0, v1, v2, v3;
        unpack2(acc[s][0], v0, v1);
        unpack2(acc[s][1], v2, v3);
        *(float4*)dst = make_float4(v0, v1, v2, v3);
        unpack2(acc[s][2], v0, v1);
        unpack2(acc[s][3], v2, v3);
        *(float4*)(dst + 4) = make_float4(v0, v1, v2, v3);
    }

    #pragma unroll
    for (int s = 0; s < 8; s++)
        #pragma unroll
        for (int jp = 0; jp < 4; jp++) acc[s][jp] = 0ull;
    #pragma unroll 4
    for (int k = 0; k < 32; k++) {
        const int K = (k >> 3) & 7;
        const float4 x0 = *(const float4*)&sX[k * 128 + ((ch0 ^ K) << 2)];
        const float4 x1 = *(const float4*)&sX[k * 128 + (((ch0 + 1) ^ K) << 2)];
        const ulonglong2 wA = __ldg((const ulonglong2*)(w1 + (32 + k) * 64 + j0));
        const ulonglong2 wB = __ldg((const ulonglong2*)(w1 + (32 + k) * 64 + j0 + 4));
        const float xs[8] = {x0.x, x0.y, x0.z, x0.w, x1.x, x1.y, x1.z, x1.w};
        #pragma unroll
        for (int s = 0; s < 8; s++) {
            const u64 x2 = pack2s(xs[s]);
            fma2(acc[s][0], x2, wA.x);
            fma2(acc[s][1], x2, wA.y);
            fma2(acc[s][2], x2, wB.x);
            fma2(acc[s][3], x2, wB.y);
        }
    }
    #pragma unroll
    for (int s = 0; s < 8; s++) {
        float* dst = g_pb + (row0 + c0 + s) * 64 + j0;
        float v0, v1, v2, v3;
        unpack2(acc[s][0], v0, v1);
        unpack2(acc[s][1], v2, v3);
        *(float4*)dst = make_float4(v0, v1, v2, v3);
        unpack2(acc[s][2], v0, v1);
        unpack2(acc[s][3], v2, v3);
        *(float4*)(dst + 4) = make_float4(v0, v1, v2, v3);
    }
}

// ---------------- bond kernel: round-10 proven version, independent blocks ----------------
__global__ void __launch_bounds__(128, 4) bond_kernel(
    const float* __restrict__ bonds, const int* __restrict__ ba1,
    const int* __restrict__ ba2,
    const float* __restrict__ w1, const float* __restrict__ w2,
    const float* __restrict__ b2v, const float* __restrict__ w3,
    const float* __restrict__ b3v, float* __restrict__ out_bonds)
{
    __shared__ __align__(16) float sW2[64 * 64];
    __shared__ __align__(16) float sX[64 * 128];

    const int tid = threadIdx.x;
    const int w = tid >> 5;
    const int lane = tid & 31;
    const int ti = lane & 3;
    const int tj = lane >> 2;
    const int j0 = tj * 8;
    const int c0 = w * 32 + ti * 8;
    const int ch0 = c0 >> 2;
    const long row0 = (long)blockIdx.x * 128;
    const int b = blockIdx.x >> 11;

    for (int i = tid; i < 1024; i += 128)
        ((float4*)sW2)[i] = __ldg(&((const float4*)w2)[i]);

    {
        const float4* p = (const float4*)(bonds + (row0 + tid) * FF);
        const int cch = tid >> 2, cw = tid & 3;
        #pragma unroll
        for (int q = 0; q < 8; q++) {
            float4 v = __ldg(&p[q]);
            float vv[4] = {v.x, v.y, v.z, v.w};
            #pragma unroll
            for (int r = 0; r < 4; r++) {
                int k = 4 * q + r;
                sX[k * 128 + (((cch ^ ((k >> 3) & 7)) << 2) | cw)] = vv[r];
            }
        }
    }
    __syncthreads();

    u64 acc[8][4];
    #pragma unroll
    for (int s = 0; s < 8; s++)
        #pragma unroll
        for (int jp = 0; jp < 4; jp++) acc[s][jp] = 0ull;

    #pragma unroll 4
    for (int k = 0; k < 32; k++) {
        const int K = (k >> 3) & 7;
        const float4 x0 = *(const float4*)&sX[k * 128 + ((ch0 ^ K) << 2)];
        const float4 x1 = *(const float4*)&sX[k * 128 + (((ch0 + 1) ^ K) << 2)];
        const ulonglong2 wA = __ldg((const ulonglong2*)(w1 + (64 + k) * 64 + j0));
        const ulonglong2 wB = __ldg((const ulonglong2*)(w1 + (64 + k) * 64 + j0 + 4));
        const float xs[8] = {x0.x, x0.y, x0.z, x0.w, x1.x, x1.y, x1.z, x1.w};
        #pragma unroll
        for (int s = 0; s < 8; s++) {
            const u64 x2 = pack2s(xs[s]);
            fma2(acc[s][0], x2, wA.x);
            fma2(acc[s][1], x2, wA.y);
            fma2(acc[s][2], x2, wB.x);
            fma2(acc[s][3], x2, wB.y);
        }
    }
    __syncthreads();

    #pragma unroll
    for (int s = 0; s < 8; s++) {
        const long row = row0 + c0 + s;
        const int a1 = __ldg(&ba1[row]);
        const int a2 = __ldg(&ba2[row]);
        const float* pap = g_pa + ((long)b * NATM + a1) * 64 + j0;
        const float* pbp = g_pb + ((long)b * NATM + a2) * 64 + j0;
        float4 A0 = __ldg((const float4*)pap), A1 = __ldg((const float4*)(pap + 4));
        float4 B0 = __ldg((const float4*)pbp), B1 = __ldg((const float4*)(pbp + 4));
        float v0, v1;
        unpack2(acc[s][0], v0, v1);
        acc[s][0] = pack2(softplus(v0 + A0.x + B0.x), softplus(v1 + A0.y + B0.y));
        unpack2(acc[s][1], v0, v1);
        acc[s][1] = pack2(softplus(v0 + A0.z + B0.z), softplus(v1 + A0.w + B0.w));
        unpack2(acc[s][2], v0, v1);
        acc[s][2] = pack2(softplus(v0 + A1.x + B1.x), softplus(v1 + A1.y + B1.y));
        unpack2(acc[s][3], v0, v1);
        acc[s][3] = pack2(softplus(v0 + A1.z + B1.z), softplus(v1 + A1.w + B1.w));
    }
    #pragma unroll
    for (int jj = 0; jj < 8; jj++) {
        const int r = j0 + jj;
        const int S = (r >> 3) & 7;
        const int jp = jj >> 1;
        float t0, t1, t2, t3, t4, t5, t6, t7, lo, hi;
        unpack2(acc[0][jp], lo, hi); t0 = (jj & 1) ? hi : lo;
        unpack2(acc[1][jp], lo, hi); t1 = (jj & 1) ? hi : lo;
        unpack2(acc[2][jp], lo, hi); t2 = (jj & 1) ? hi : lo;
        unpack2(acc[3][jp], lo, hi); t3 = (jj & 1) ? hi : lo;
        unpack2(acc[4][jp], lo, hi); t4 = (jj & 1) ? hi : lo;
        unpack2(acc[5][jp], lo, hi); t5 = (jj & 1) ? hi : lo;
        unpack2(acc[6][jp], lo, hi); t6 = (jj & 1) ? hi : lo;
        unpack2(acc[7][jp], lo, hi); t7 = (jj & 1) ? hi : lo;
        *(float4*)&sX[r * 128 + ((ch0 ^ S) << 2)] = make_float4(t0, t1, t2, t3);
        *(float4*)&sX[r * 128 + (((ch0 + 1) ^ S) << 2)] = make_float4(t4, t5, t6, t7);
    }
    __syncthreads();

    #pragma unroll
    for (int s = 0; s < 8; s++)
        #pragma unroll
        for (int jp = 0; jp < 4; jp++) acc[s][jp] = 0ull;
    for (int kk = 0; kk < 64; kk += 8) {
        const int K = kk >> 3;
        const float* xr = &sX[kk * 128];
        const float* wr = &sW2[kk * 64];
        #pragma unroll
        for (int u = 0; u < 8; u++) {
            const float4 x0 = *(const float4*)&xr[u * 128 + ((ch0 ^ K) << 2)];
            const float4 x1 = *(const float4*)&xr[u * 128 + (((ch0 + 1) ^ K) << 2)];
            const ulonglong2 wA = *(const ulonglong2*)&wr[u * 64 + j0];
            const ulonglong2 wB = *(const ulonglong2*)&wr[u * 64 + j0 + 4];
            const float xs[8] = {x0.x, x0.y, x0.z, x0.w, x1.x, x1.y, x1.z, x1.w};
            #pragma unroll
            for (int s = 0; s < 8; s++) {
                const u64 x2 = pack2s(xs[s]);
                fma2(acc[s][0], x2, wA.x);
                fma2(acc[s][1], x2, wA.y);
                fma2(acc[s][2], x2, wB.x);
                fma2(acc[s][3], x2, wB.y);
            }
        }
    }
    __syncthreads();

    {
        float4 bA = __ldg((const float4*)(b2v + j0));
        float4 bB = __ldg((const float4*)(b2v + j0 + 4));
        #pragma unroll
        for (int s = 0; s < 8; s++) {
            float v0, v1;
            unpack2(acc[s][0], v0, v1);
            acc[s][0] = pack2(softplus(v0 + bA.x), softplus(v1 + bA.y));
            unpack2(acc[s][1], v0, v1);
            acc[s][1] = pack2(softplus(v0 + bA.z), softplus(v1 + bA.w));
            unpack2(acc[s][2], v0, v1);
            acc[s][2] = pack2(softplus(v0 + bB.x), softplus(v1 + bB.y));
            unpack2(acc[s][3], v0, v1);
            acc[s][3] = pack2(softplus(v0 + bB.z), softplus(v1 + bB.w));
        }
        #pragma unroll
        for (int jj = 0; jj < 8; jj++) {
            const int r = j0 + jj;
            const int S = (r >> 3) & 7;
            const int jp = jj >> 1;
            float t0, t1, t2, t3, t4, t5, t6, t7, lo, hi;
            unpack2(acc[0][jp], lo, hi); t0 = (jj & 1) ? hi : lo;
            unpack2(acc[1][jp], lo, hi); t1 = (jj & 1) ? hi : lo;
            unpack2(acc[2][jp], lo, hi); t2 = (jj & 1) ? hi : lo;
            unpack2(acc[3][jp], lo, hi); t3 = (jj & 1) ? hi : lo;
            unpack2(acc[4][jp], lo, hi); t4 = (jj & 1) ? hi : lo;
            unpack2(acc[5][jp], lo, hi); t5 = (jj & 1) ? hi : lo;
            unpack2(acc[6][jp], lo, hi); t6 = (jj & 1) ? hi : lo;
            unpack2(acc[7][jp], lo, hi); t7 = (jj & 1) ? hi : lo;
            *(float4*)&sX[r * 128 + ((ch0 ^ S) << 2)] = make_float4(t0, t1, t2, t3);
            *(float4*)&sX[r * 128 + (((ch0 + 1) ^ S) << 2)] = make_float4(t4, t5, t6, t7);
        }
    }
    __syncthreads();

    const int j0b = tj * 4;
    u64 a3[8][2];
    #pragma unroll
    for (int s = 0; s < 8; s++) { a3[s][0] = 0ull; a3[s][1] = 0ull; }
    for (int kk = 0; kk < 64; kk += 8) {
        const int K = kk >> 3;
        const float* xr = &sX[kk * 128];
        #pragma unroll
        for (int u = 0; u < 8; u++) {
            const float4 x0 = *(const float4*)&xr[u * 128 + ((ch0 ^ K) << 2)];
            const float4 x1 = *(const float4*)&xr[u * 128 + (((ch0 + 1) ^ K) << 2)];
            const ulonglong2 wv = __ldg((const ulonglong2*)(w3 + (kk + u) * 32 + j0b));
            const float xs[8] = {x0.x, x0.y, x0.z, x0.w, x1.x, x1.y, x1.z, x1.w};
            #pragma unroll
            for (int s = 0; s < 8; s++) {
                const u64 x2 = pack2s(xs[s]);
                fma2(a3[s][0], x2, wv.x);
                fma2(a3[s][1], x2, wv.y);
            }
        }
    }

    {
        float4 b3q = __ldg((const float4*)(b3v + j0b));
        #pragma unroll
        for (int s = 0; s < 8; s++) {
            const long row = row0 + c0 + s;
            const int a1 = __ldg(&ba1[row]);
            float o0, o1, o2, o3;
            unpack2(a3[s][0], o0, o1);
            unpack2(a3[s][1], o2, o3);
            o0 = softplus(o0 + b3q.x);
            o1 = softplus(o1 + b3q.y);
            o2 = softplus(o2 + b3q.z);
            o3 = softplus(o3 + b3q.w);
            *(float4*)(out_bonds + row * FF + j0b) = make_float4(o0, o1, o2, o3);
            red4(g_bta + ((long)b * NATM + a1) * FF + j0b, o0, o1, o2, o3);
            if (tj == 0) atomicAdd(&g_cnt[b * NATM + a1], 1.0f);
        }
    }
}

// ---------------- atom main kernel (round-12 proven) ----------------
__global__ void __launch_bounds__(128, 4) atom_main_kernel(
    const float* __restrict__ atoms, const float* __restrict__ state,
    const float* __restrict__ w1, const float* __restrict__ b1,
    const float* __restrict__ w2, const float* __restrict__ b2v,
    const float* __restrict__ w3, const float* __restrict__ b3v,
    float* __restrict__ out_atoms)
{
    __shared__ __align__(16) float sW2[64 * 64];
    __shared__ __align__(16) float sX[64 * 128];
    __shared__ __align__(16) float s_hst[64];

    const int tid = threadIdx.x;
    const int w = tid >> 5;
    const int lane = tid & 31;
    const int ti = lane & 3;
    const int tj = lane >> 2;
    const int j0 = tj * 8;
    const int c0 = w * 32 + ti * 8;
    const int ch0 = c0 >> 2;
    const long row0 = (long)blockIdx.x * 128;
    const int b = blockIdx.x >> 6;

    for (int i = tid; i < 1024; i += 128)
        ((float4*)sW2)[i] = __ldg(&((const float4*)w2)[i]);

    if (tid < 64) {
        float acc = __ldg(&b1[tid]);
        #pragma unroll
        for (int k = 0; k < 32; k++)
            acc = fmaf(__ldg(&state[b * FF + k]), __ldg(&w1[(64 + k) * 64 + tid]), acc);
        s_hst[tid] = acc;
    }

    {
        const long grow = row0 + tid;
        const float invc = 1.0f / g_cnt[grow];
        const int cch = tid >> 2, cw = tid & 3;
        const float4* pb = (const float4*)(g_bta + grow * FF);
        const float4* pa = (const float4*)(atoms + grow * FF);
        #pragma unroll
        for (int q = 0; q < 8; q++) {
            float4 v = __ldg(&pb[q]);
            float vv[4] = {v.x * invc, v.y * invc, v.z * invc, v.w * invc};
            #pragma unroll
            for (int r = 0; r < 4; r++) {
                int k = 4 * q + r;
                sX[k * 128 + (((cch ^ ((k >> 3) & 7)) << 2) | cw)] = vv[r];
            }
        }
        #pragma unroll
        for (int q = 0; q < 8; q++) {
            float4 v = __ldg(&pa[q]);
            float vv[4] = {v.x, v.y, v.z, v.w};
            #pragma unroll
            for (int r = 0; r < 4; r++) {
                int k = 32 + 4 * q + r;
                sX[k * 128 + (((cch ^ ((k >> 3) & 7)) << 2) | cw)] = vv[r];
            }
        }
    }
    __syncthreads();

    u64 acc[8][4];
    #pragma unroll
    for (int s = 0; s < 8; s++)
        #pragma unroll
        for (int jp = 0; jp < 4; jp++) acc[s][jp] = 0ull;

    for (int kk = 0; kk < 64; kk += 8) {
        const int K = kk >> 3;
        const float* xr = &sX[kk * 128];
        #pragma unroll
        for (int u = 0; u < 8; u++) {
            const float4 x0 = *(const float4*)&xr[u * 128 + ((ch0 ^ K) << 2)];
            const float4 x1 = *(const float4*)&xr[u * 128 + (((ch0 + 1) ^ K) << 2)];
            const ulonglong2 wA = __ldg((const ulonglong2*)(w1 + (kk + u) * 64 + j0));
            const ulonglong2 wB = __ldg((const ulonglong2*)(w1 + (kk + u) * 64 + j0 + 4));
            const float xs[8] = {x0.x, x0.y, x0.z, x0.w, x1.x, x1.y, x1.z, x1.w};
            #pragma unroll
            for (int s = 0; s < 8; s++) {
                const u64 x2 = pack2s(xs[s]);
                fma2(acc[s][0], x2, wA.x);
                fma2(acc[s][1], x2, wA.y);
                fma2(acc[s][2], x2, wB.x);
                fma2(acc[s][3], x2, wB.y);
            }
        }
    }
    __syncthreads();

    {
        const float4 hA = *(const float4*)&s_hst[j0];
        const float4 hB = *(const float4*)&s_hst[j0 + 4];
        #pragma unroll
        for (int s = 0; s < 8; s++) {
            float v0, v1;
            unpack2(acc[s][0], v0, v1);
            acc[s][0] = pack2(softplus(v0 + hA.x), softplus(v1 + hA.y));
            unpack2(acc[s][1], v0, v1);
            acc[s][1] = pack2(softplus(v0 + hA.z), softplus(v1 + hA.w));
            unpack2(acc[s][2], v0, v1);
            acc[s][2] = pack2(softplus(v0 + hB.x), softplus(v1 + hB.y));
            unpack2(acc[s][3], v0, v1);
            acc[s][3] = pack2(softplus(v0 + hB.z), softplus(v1 + hB.w));
        }
        #pragma unroll
        for (int jj = 0; jj < 8; jj++) {
            const int r = j0 + jj;
            const int S = (r >> 3) & 7;
            const int jp = jj >> 1;
            float t0, t1, t2, t3, t4, t5, t6, t7, lo, hi;
            unpack2(acc[0][jp], lo, hi); t0 = (jj & 1) ? hi : lo;
            unpack2(acc[1][jp], lo, hi); t1 = (jj & 1) ? hi : lo;
            unpack2(acc[2][jp], lo, hi); t2 = (jj & 1) ? hi : lo;
            unpack2(acc[3][jp], lo, hi); t3 = (jj & 1) ? hi : lo;
            unpack2(acc[4][jp], lo, hi); t4 = (jj & 1) ? hi : lo;
            unpack2(acc[5][jp], lo, hi); t5 = (jj & 1) ? hi : lo;
            unpack2(acc[6][jp], lo, hi); t6 = (jj & 1) ? hi : lo;
            unpack2(acc[7][jp], lo, hi); t7 = (jj & 1) ? hi : lo;
            *(float4*)&sX[r * 128 + ((ch0 ^ S) << 2)] = make_float4(t0, t1, t2, t3);
            *(float4*)&sX[r * 128 + (((ch0 + 1) ^ S) << 2)] = make_float4(t4, t5, t6, t7);
        }
    }
    __syncthreads();

    #pragma unroll
    for (int s = 0; s < 8; s++)
        #pragma unroll
        for (int jp = 0; jp < 4; jp++) acc[s][jp] = 0ull;
    for (int kk = 0; kk < 64; kk += 8) {
        const int K = kk >> 3;
        const float* xr = &sX[kk * 128];
        const float* wr = &sW2[kk * 64];
        #pragma unroll
        for (int u = 0; u < 8; u++) {
            const float4 x0 = *(const float4*)&xr[u * 128 + ((ch0 ^ K) << 2)];
            const float4 x1 = *(const float4*)&xr[u * 128 + (((ch0 + 1) ^ K) << 2)];
            const ulonglong2 wA = *(const ulonglong2*)&wr[u * 64 + j0];
            const ulonglong2 wB = *(const ulonglong2*)&wr[u * 64 + j0 + 4];
            const float xs[8] = {x0.x, x0.y, x0.z, x0.w, x1.x, x1.y, x1.z, x1.w};
            #pragma unroll
            for (int s = 0; s < 8; s++) {
                const u64 x2 = pack2s(xs[s]);
                fma2(acc[s][0], x2, wA.x);
                fma2(acc[s][1], x2, wA.y);
                fma2(acc[s][2], x2, wB.x);
                fma2(acc[s][3], x2, wB.y);
            }
        }
    }
    __syncthreads();

    {
        float4 bA = __ldg((const float4*)(b2v + j0));
        float4 bB = __ldg((const float4*)(b2v + j0 + 4));
        #pragma unroll
        for (int s = 0; s < 8; s++) {
            float v0, v1;
            unpack2(acc[s][0], v0, v1);
            acc[s][0] = pack2(softplus(v0 + bA.x), softplus(v1 + bA.y));
            unpack2(acc[s][1], v0, v1);
            acc[s][1] = pack2(softplus(v0 + bA.z), softplus(v1 + bA.w));
            unpack2(acc[s][2], v0, v1);
            acc[s][2] = pack2(softplus(v0 + bB.x), softplus(v1 + bB.y));
            unpack2(acc[s][3], v0, v1);
            acc[s][3] = pack2(softplus(v0 + bB.z), softplus(v1 + bB.w));
        }
        #pragma unroll
        for (int jj = 0; jj < 8; jj++) {
            const int r = j0 + jj;
            const int S = (r >> 3) & 7;
            const int jp = jj >> 1;
            float t0, t1, t2, t3, t4, t5, t6, t7, lo, hi;
            unpack2(acc[0][jp], lo, hi); t0 = (jj & 1) ? hi : lo;
            unpack2(acc[1][jp], lo, hi); t1 = (jj & 1) ? hi : lo;
            unpack2(acc[2][jp], lo, hi); t2 = (jj & 1) ? hi : lo;
            unpack2(acc[3][jp], lo, hi); t3 = (jj & 1) ? hi : lo;
            unpack2(acc[4][jp], lo, hi); t4 = (jj & 1) ? hi : lo;
            unpack2(acc[5][jp], lo, hi); t5 = (jj & 1) ? hi : lo;
            unpack2(acc[6][jp], lo, hi); t6 = (jj & 1) ? hi : lo;
            unpack2(acc[7][jp], lo, hi); t7 = (jj & 1) ? hi : lo;
            *(float4*)&sX[r * 128 + ((ch0 ^ S) << 2)] = make_float4(t0, t1, t2, t3);
            *(float4*)&sX[r * 128 + (((ch0 + 1) ^ S) << 2)] = make_float4(t4, t5, t6, t7);
        }
    }
    __syncthreads();

    const int j0b = tj * 4;
    u64 a3[8][2];
    #pragma unroll
    for (int s = 0; s < 8; s++) { a3[s][0] = 0ull; a3[s][1] = 0ull; }
    for (int kk = 0; kk < 64; kk += 8) {
        const int K = kk >> 3;
        const float* xr = &sX[kk * 128];
        #pragma unroll
        for (int u = 0; u < 8; u++) {
            const float4 x0 = *(const float4*)&xr[u * 128 + ((ch0 ^ K) << 2)];
            const float4 x1 = *(const float4*)&xr[u * 128 + (((ch0 + 1) ^ K) << 2)];
            const ulonglong2 wv = __ldg((const ulonglong2*)(w3 + (kk + u) * 32 + j0b));
            const float xs[8] = {x0.x, x0.y, x0.z, x0.w, x1.x, x1.y, x1.z, x1.w};
            #pragma unroll
            for (int s = 0; s < 8; s++) {
                const u64 x2 = pack2s(xs[s]);
                fma2(a3[s][0], x2, wv.x);
                fma2(a3[s][1], x2, wv.y);
            }
        }
    }

    {
        float4 b3q = __ldg((const float4*)(b3v + j0b));
        #pragma unroll
        for (int s = 0; s < 8; s++) {
            const long row = row0 + c0 + s;
            float o0, o1, o2, o3;
            unpack2(a3[s][0], o0, o1);
            unpack2(a3[s][1], o2, o3);
            o0 = softplus(o0 + b3q.x);
            o1 = softplus(o1 + b3q.y);
            o2 = softplus(o2 + b3q.z);
            o3 = softplus(o3 + b3q.w);
            *(float4*)(out_atoms + row * FF + j0b) = make_float4(o0, o1, o2, o3);
        }
    }
}

// ---------------- reduce + state (fused): 32 blocks; last block runs u-MLP ----------------
__global__ void __launch_bounds__(256) reduce_state_kernel(
    const float* __restrict__ out_atoms, const float* __restrict__ state,
    const float* __restrict__ w1, const float* __restrict__ b1,
    const float* __restrict__ w2, const float* __restrict__ b2,
    const float* __restrict__ w3, const float* __restrict__ b3,
    float* __restrict__ out_state)
{
    __shared__ float red[2][8][32];
    __shared__ unsigned int s_ticket;
    __shared__ float s_u[BB][96];
    __shared__ float s_h1[BB][64];
    __shared__ float s_h2[BB][64];

    const int blk = blockIdx.x;
    const int bb = blk >> 3;
    const int seg = blk & 7;
    const int t = threadIdx.x;
    const int f = t & 31;
    const int g = t >> 5;
    const long base = ((long)bb * NATM + seg * 1024) * FF;
    float sb = 0.0f, sa = 0.0f;
    for (int r = g; r < 1024; r += 8) {
        sb += g_bta[base + (long)r * FF + f];
        sa += __ldg(&out_atoms[base + (long)r * FF + f]);
    }
    red[0][g][f] = sb;
    red[1][g][f] = sa;
    __syncthreads();
    if (g == 0) {
        float vb = 0.0f, va = 0.0f;
        #pragma unroll
        for (int i = 0; i < 8; i++) { vb += red[0][i][f]; va += red[1][i][f]; }
        g_part[0][blk][f] = vb;
        g_part[1][blk][f] = va;
    }
    __threadfence();
    __syncthreads();
    if (t == 0) s_ticket = atomicAdd(&g_done, 1u);
    __syncthreads();
    if (s_ticket != 31u) return;

    const int b = t >> 6;
    const int u = t & 63;
    if (u < 32) {
        float vb = 0.0f, va = 0.0f;
        #pragma unroll
        for (int s = 0; s < 8; s++) {
            vb += g_part[0][b * 8 + s][u];
            va += g_part[1][b * 8 + s][u];
        }
        s_u[b][u]      = vb * (1.0f / NBND);
        s_u[b][32 + u] = va * (1.0f / NATM);
        s_u[b][64 + u] = __ldg(&state[b * FF + u]);
    }
    __syncthreads();
    {
        float acc = __ldg(&b1[u]);
        for (int k = 0; k < 96; k++) acc = fmaf(s_u[b][k], __ldg(&w1[k * 64 + u]), acc);
        s_h1[b][u] = softplus(acc);
    }
    __syncthreads();
    {
        float acc = __ldg(&b2[u]);
        for (int k = 0; k < 64; k++) acc = fmaf(s_h1[b][k], __ldg(&w2[k * 64 + u]), acc);
        s_h2[b][u] = softplus(acc);
    }
    __syncthreads();
    if (u < 32) {
        float acc = __ldg(&b3[u]);
        for (int k = 0; k < 64; k++) acc = fmaf(s_h2[b][k], __ldg(&w3[k * 32 + u]), acc);
        out_state[b * FF + u] = softplus(acc);
    }
}

extern "C" void kernel_launch(void* const* d_in, const int* in_sizes, int n_in,
                              void* d_out, int out_size)
{
    const float* bonds = (const float*)d_in[0];
    const int*   ba1   = (const int*)d_in[1];
    const int*   ba2   = (const int*)d_in[2];
    const float* atoms = (const float*)d_in[3];
    const float* state = (const float*)d_in[4];
    const float* ew1 = (const float*)d_in[5];
    const float* eb1 = (const float*)d_in[6];
    const float* ew2 = (const float*)d_in[7];
    const float* eb2 = (const float*)d_in[8];
    const float* ew3 = (const float*)d_in[9];
    const float* eb3 = (const float*)d_in[10];
    const float* vw1 = (const float*)d_in[11];
    const float* vb1 = (const float*)d_in[12];
    const float* vw2 = (const float*)d_in[13];
    const float* vb2 = (const float*)d_in[14];
    const float* vw3 = (const float*)d_in[15];
    const float* vb3 = (const float*)d_in[16];
    const float* uw1 = (const float*)d_in[17];
    const float* ub1 = (const float*)d_in[18];
    const float* uw2 = (const float*)d_in[19];
    const float* ub2 = (const float*)d_in[20];
    const float* uw3 = (const float*)d_in[21];
    const float* ub3 = (const float*)d_in[22];

    float* out = (float*)d_out;
    float* out_bonds = out;
    float* out_atoms = out + (long)BB * NBND * FF;
    float* out_state = out_atoms + (long)BB * NATM * FF;

    zero_kernel<<<(BB * NATM * FF + 255) / 256, 256>>>();
    atom_pre_kernel<<<(BB * NATM) / 128, 128>>>(atoms, ew1, eb1, state);
    bond_kernel<<<(BB * NBND) / 128, 128>>>(bonds, ba1, ba2,
                                            ew1, ew2, eb2, ew3, eb3, out_bonds);
    atom_main_kernel<<<(BB * NATM) / 128, 128>>>(atoms, state,
                                                 vw1, vb1, vw2, vb2, vw3, vb3, out_atoms);
    reduce_state_kernel<<<32, 256>>>(out_atoms, state, uw1, ub1, uw2, ub2,
                                     uw3, ub3, out_state);
}